// round 7
// baseline (speedup 1.0000x reference)
#include <cuda_runtime.h>
#include <cstdint>

#define NN   524288
#define BSEG 4096
#define SEG  128
#define DIN  128
#define HH   256

// Scratch for intermediate activations — static device arrays per alloc rules.
__device__ float g_h1[(size_t)NN * HH];
__device__ float g_h2[(size_t)NN * HH];

// ---------------------------------------------------------------------------
// Fused Linear + bias + ReLU:  C[N,256] = relu(A @ W + b), EXACT fp32
// (matches CPU-XLA reference dots). 128x128 tile, BK=16, 8x8/thread, 256 thr.
// ---------------------------------------------------------------------------
__global__ void __launch_bounds__(256, 2) gemm_relu_kernel(
    const float* __restrict__ A, const float* __restrict__ W,
    const float* __restrict__ bias, float* __restrict__ C, int Hin)
{
    __shared__ float As[16][132];   // padded; stored transposed As[k][m]
    __shared__ float Ws[16][128];   // Ws[k][n]

    const int t    = threadIdx.x;
    const int row0 = blockIdx.x * 128;
    const int col0 = blockIdx.y * 128;
    const int tx = t & 15, ty = t >> 4;
    const int ar = t >> 2, ak = (t & 3) << 2;
    const int wk = t >> 4, wc = (t & 15) << 3;

    float acc[8][8];
#pragma unroll
    for (int i = 0; i < 8; i++)
#pragma unroll
        for (int j = 0; j < 8; j++) acc[i][j] = 0.f;

    for (int k0 = 0; k0 < Hin; k0 += 16) {
#pragma unroll
        for (int rr = 0; rr < 2; rr++) {
            int r = ar + rr * 64;
            float4 v = *(const float4*)(A + (size_t)(row0 + r) * Hin + k0 + ak);
            As[ak + 0][r] = v.x; As[ak + 1][r] = v.y;
            As[ak + 2][r] = v.z; As[ak + 3][r] = v.w;
        }
        const float* wrow = W + (size_t)(k0 + wk) * HH + col0 + wc;
        *(float4*)&Ws[wk][wc]     = *(const float4*)(wrow);
        *(float4*)&Ws[wk][wc + 4] = *(const float4*)(wrow + 4);
        __syncthreads();

#pragma unroll
        for (int k = 0; k < 16; k++) {
            float a[8], b[8];
            *(float4*)(a)     = *(const float4*)&As[k][ty * 8];
            *(float4*)(a + 4) = *(const float4*)&As[k][ty * 8 + 4];
            *(float4*)(b)     = *(const float4*)&Ws[k][tx * 8];
            *(float4*)(b + 4) = *(const float4*)&Ws[k][tx * 8 + 4];
#pragma unroll
            for (int i = 0; i < 8; i++)
#pragma unroll
                for (int j = 0; j < 8; j++)
                    acc[i][j] = fmaf(a[i], b[j], acc[i][j]);
        }
        __syncthreads();
    }

#pragma unroll
    for (int i = 0; i < 8; i++) {
        int r = row0 + ty * 8 + i;
#pragma unroll
        for (int j = 0; j < 8; j += 4) {
            int c = col0 + tx * 8 + j;
            float4 o;
            o.x = fmaxf(acc[i][j + 0] + bias[c + 0], 0.f);
            o.y = fmaxf(acc[i][j + 1] + bias[c + 1], 0.f);
            o.z = fmaxf(acc[i][j + 2] + bias[c + 2], 0.f);
            o.w = fmaxf(acc[i][j + 3] + bias[c + 3], 0.f);
            *(float4*)(C + (size_t)r * HH + c) = o;
        }
    }
}

// ---------------------------------------------------------------------------
// JAX PARTITIONABLE threefry-2x32, key(42): per element i (uint64 iota),
// lanes (hi=0)+k0, (lo=i)+k1; 20 rounds; 32-bit draw = out0 ^ out1.
// ---------------------------------------------------------------------------
__device__ __forceinline__ uint32_t rotl32(uint32_t x, int d) {
    return (x << d) | (x >> (32 - d));
}

__device__ __forceinline__ float jax_uniform_u(uint32_t i)
{
    const uint32_t k0 = 0u, k1 = 42u;
    const uint32_t k2 = 0x1BD11BDAu ^ k0 ^ k1;
    uint32_t x0 = k0;          // counts_hi = 0, + key0
    uint32_t x1 = i + k1;      // counts_lo = i, + key1
#define TF_ROUND(r) { x0 += x1; x1 = rotl32(x1, (r)) ^ x0; }
#define TF_G(a,b,c,d) TF_ROUND(a) TF_ROUND(b) TF_ROUND(c) TF_ROUND(d)
    TF_G(13, 15, 26, 6)   x0 += k1; x1 += k2 + 1u;
    TF_G(17, 29, 16, 24)  x0 += k2; x1 += k0 + 2u;
    TF_G(13, 15, 26, 6)   x0 += k0; x1 += k1 + 3u;
    TF_G(17, 29, 16, 24)  x0 += k1; x1 += k2 + 4u;
    TF_G(13, 15, 26, 6)   x0 += k2; x1 += k0 + 5u;
#undef TF_G
#undef TF_ROUND
    uint32_t bits = x0 ^ x1;   // sub-64-bit lane combine
    float f = __uint_as_float((bits >> 9) | 0x3f800000u) - 1.0f;
    float u = f * (1.0f - 1e-20f) + 1e-20f;
    return fmaxf(u, 1e-20f);
}

// ---------------------------------------------------------------------------
// Per-segment: logits = h @ Wf + bf (exact fp32), softmax over 128 nodes,
// Gumbel-max sample. One 128-thread block per segment. Tie-break: higher index.
// ---------------------------------------------------------------------------
__global__ void __launch_bounds__(SEG) final_kernel(
    const float* __restrict__ h, const float* __restrict__ Wf,
    const float* __restrict__ bf, float* __restrict__ out)
{
    __shared__ float wfs[HH];
    __shared__ float red[SEG];
    __shared__ int   redi[SEG];
    __shared__ float sprob[SEG];
    __shared__ float s_sum;

    const int seg = blockIdx.x;
    const int t   = threadIdx.x;

    for (int k = t; k < HH; k += SEG) wfs[k] = Wf[k];
    __syncthreads();

    const int node = seg * SEG + t;
    const float4* hr = (const float4*)(h + (size_t)node * HH);
    const float4* wr = (const float4*)wfs;
    float acc = 0.f;
#pragma unroll
    for (int k = 0; k < HH / 4; k++) {
        float4 v = hr[k];
        float4 w = wr[k];
        acc += v.x * w.x + v.y * w.y + v.z * w.z + v.w * w.w;
    }
    float logit = acc + bf[0];
    float e = expf(logit);

    red[t] = e;
    __syncthreads();
#pragma unroll
    for (int s = SEG / 2; s > 0; s >>= 1) {
        if (t < s) red[t] += red[t + s];
        __syncthreads();
    }
    if (t == 0) s_sum = red[0];
    __syncthreads();

    float prob = e / s_sum;
    sprob[t] = prob;

    float u = jax_uniform_u((uint32_t)node);
    float g = -logf(-logf(u));
    float score = logf(prob) + g;

    red[t] = score; redi[t] = t;
    __syncthreads();
#pragma unroll
    for (int s = SEG / 2; s > 0; s >>= 1) {
        if (t < s) {
            float s2 = red[t + s]; int i2 = redi[t + s];
            if (s2 > red[t] || (s2 == red[t] && i2 > redi[t])) { red[t] = s2; redi[t] = i2; }
        }
        __syncthreads();
    }

    if (t == 0) {
        int win = redi[0];
        out[seg]            = sprob[win];                  // p
        out[BSEG + seg]     = (float)win;                  // actions (local idx)
        out[2 * BSEG + seg] = (float)(seg * SEG + win);    // shifted_actions
    }
}

// ---------------------------------------------------------------------------
extern "C" void kernel_launch(void* const* d_in, const int* in_sizes, int n_in,
                              void* d_out, int out_size)
{
    (void)out_size;
    // Input layout detection. Insertion order: X,W0,b0,W1,b1,W2,b2,Wf,bf,batch.
    // Alphabetical fallback: W0,W1,W2,Wf,X,b0,b1,b2,batch,bf.
    // X (size NN*DIN = 67108864) uniquely identifies the layout.
    const float *X, *W0, *b0, *W1, *b1, *W2, *b2, *Wf, *bf;
    if (n_in > 0 && in_sizes[0] == NN * DIN) {
        X  = (const float*)d_in[0];
        W0 = (const float*)d_in[1]; b0 = (const float*)d_in[2];
        W1 = (const float*)d_in[3]; b1 = (const float*)d_in[4];
        W2 = (const float*)d_in[5]; b2 = (const float*)d_in[6];
        Wf = (const float*)d_in[7]; bf = (const float*)d_in[8];
    } else {
        W0 = (const float*)d_in[0];
        W1 = (const float*)d_in[1];
        W2 = (const float*)d_in[2];
        Wf = (const float*)d_in[3];
        X  = (const float*)d_in[4];
        b0 = (const float*)d_in[5]; b1 = (const float*)d_in[6];
        b2 = (const float*)d_in[7]; bf = (const float*)d_in[9];
    }
    float* out = (float*)d_out;

    float *h1, *h2;
    cudaGetSymbolAddress((void**)&h1, g_h1);
    cudaGetSymbolAddress((void**)&h2, g_h2);

    dim3 grid(NN / 128, HH / 128);
    gemm_relu_kernel<<<grid, 256>>>(X,  W0, b0, h1, DIN);
    gemm_relu_kernel<<<grid, 256>>>(h1, W1, b1, h2, HH);
    gemm_relu_kernel<<<grid, 256>>>(h2, W2, b2, h1, HH);
    final_kernel<<<BSEG, SEG>>>(h1, Wf, bf, out);
}

// round 8
// speedup vs baseline: 1.3575x; 1.3575x over previous
#include <cuda_runtime.h>
#include <cstdint>

#define NN   524288
#define BSEG 4096
#define SEG  128
#define DIN  128
#define HH   256

// Static device scratch (alloc-free rules).
__device__ float g_h1[(size_t)NN * HH];
__device__ float g_h2[(size_t)NN * HH];
__device__ float g_part[(size_t)8 * NN];   // per-(colblock,warp_n) logit partials

// ---------------------------------------------------------------------------
// 3xTF32 split: x = hi + lo with hi = tf32(x), lo = tf32(x - hi).
// hi*hi + hi*lo + lo*hi reproduces fp32 products to ~2^-22 relative.
// ---------------------------------------------------------------------------
__device__ __forceinline__ void split_tf32(float x, uint32_t& hi, uint32_t& lo) {
    float h, l;
    asm("cvt.rna.tf32.f32 %0, %1;" : "=f"(h) : "f"(x));
    float d = x - h;
    asm("cvt.rna.tf32.f32 %0, %1;" : "=f"(l) : "f"(d));
    hi = __float_as_uint(h);
    lo = __float_as_uint(l);
}

__device__ __forceinline__ void mma8(float* c,
    uint32_t a0, uint32_t a1, uint32_t a2, uint32_t a3,
    uint32_t b0, uint32_t b1)
{
    asm volatile("mma.sync.aligned.m16n8k8.row.col.f32.tf32.tf32.f32 "
        "{%0,%1,%2,%3}, {%4,%5,%6,%7}, {%8,%9}, {%0,%1,%2,%3};"
        : "+f"(c[0]), "+f"(c[1]), "+f"(c[2]), "+f"(c[3])
        : "r"(a0), "r"(a1), "r"(a2), "r"(a3), "r"(b0), "r"(b1));
}

// ---------------------------------------------------------------------------
// tf32x3 tensor-core GEMM + bias + ReLU.
// C[N,256] = relu(A[N,HIN] @ W[HIN,256] + b).
// Block 128(M) x 128(N), BK=32. 8 warps: warp tile 64x32 (4 m-tiles x 4 n-tiles
// of m16n8k8). FUSE=true: layer-3 epilogue also dots rows with Wf and emits
// per-(colblock,warp_n) partial logits into g_part (deterministic, no atomics).
// ---------------------------------------------------------------------------
template<int HIN, bool FUSE>
__global__ void __launch_bounds__(256, 2) gemm_tf32(
    const float* __restrict__ A, const float* __restrict__ W,
    const float* __restrict__ bias, const float* __restrict__ Wf,
    float* __restrict__ C)
{
    __shared__ float As[128][36];    // stride 36: conflict-free frag loads
    __shared__ float Bs[32][136];    // stride 136: conflict-free frag loads

    const int t    = threadIdx.x;
    const int lane = t & 31;
    const int w    = t >> 5;
    const int wm   = w >> 2;         // 0..1  (64 rows each)
    const int wn   = w & 3;          // 0..3  (32 cols each)
    const int row0 = blockIdx.y * 128;
    const int col0 = blockIdx.x * 128;

    float acc[4][4][4];
#pragma unroll
    for (int i = 0; i < 4; i++)
#pragma unroll
        for (int j = 0; j < 4; j++)
#pragma unroll
            for (int q = 0; q < 4; q++) acc[i][j][q] = 0.f;

    for (int k0 = 0; k0 < HIN; k0 += 32) {
        // Load A tile 128x32
#pragma unroll
        for (int p = 0; p < 4; p++) {
            int idx = p * 256 + t;
            int r = idx >> 3, c4 = (idx & 7) * 4;
            float4 v = *(const float4*)(A + (size_t)(row0 + r) * HIN + k0 + c4);
            *(float4*)&As[r][c4] = v;
        }
        // Load B tile 32x128
#pragma unroll
        for (int p = 0; p < 4; p++) {
            int idx = p * 256 + t;
            int r = idx >> 5, c4 = (idx & 31) * 4;
            float4 v = *(const float4*)(W + (size_t)(k0 + r) * HH + col0 + c4);
            *(float4*)&Bs[r][c4] = v;
        }
        __syncthreads();

#pragma unroll
        for (int kk = 0; kk < 32; kk += 8) {
            uint32_t ah[4][4], al[4][4];
#pragma unroll
            for (int i = 0; i < 4; i++) {
                int r = wm * 64 + i * 16 + (lane >> 2);
                int c = kk + (lane & 3);
                split_tf32(As[r][c],         ah[i][0], al[i][0]);
                split_tf32(As[r + 8][c],     ah[i][1], al[i][1]);
                split_tf32(As[r][c + 4],     ah[i][2], al[i][2]);
                split_tf32(As[r + 8][c + 4], ah[i][3], al[i][3]);
            }
#pragma unroll
            for (int j = 0; j < 4; j++) {
                int n  = wn * 32 + j * 8 + (lane >> 2);
                int kr = kk + (lane & 3);
                uint32_t bh0, bl0, bh1, bl1;
                split_tf32(Bs[kr][n],     bh0, bl0);
                split_tf32(Bs[kr + 4][n], bh1, bl1);
#pragma unroll
                for (int i = 0; i < 4; i++)
                    mma8(acc[i][j], ah[i][0], ah[i][1], ah[i][2], ah[i][3], bh0, bh1);
#pragma unroll
                for (int i = 0; i < 4; i++)
                    mma8(acc[i][j], ah[i][0], ah[i][1], ah[i][2], ah[i][3], bl0, bl1);
#pragma unroll
                for (int i = 0; i < 4; i++)
                    mma8(acc[i][j], al[i][0], al[i][1], al[i][2], al[i][3], bh0, bh1);
            }
        }
        __syncthreads();
    }

    if (!FUSE) {
        // bias + ReLU + store to C
#pragma unroll
        for (int i = 0; i < 4; i++) {
            int r = row0 + wm * 64 + i * 16 + (lane >> 2);
#pragma unroll
            for (int j = 0; j < 4; j++) {
                int c = col0 + wn * 32 + j * 8 + 2 * (lane & 3);
                float b0v = bias[c], b1v = bias[c + 1];
                float2 v0 = { fmaxf(acc[i][j][0] + b0v, 0.f),
                              fmaxf(acc[i][j][1] + b1v, 0.f) };
                float2 v1 = { fmaxf(acc[i][j][2] + b0v, 0.f),
                              fmaxf(acc[i][j][3] + b1v, 0.f) };
                *(float2*)(C + (size_t)r * HH + c)       = v0;
                *(float2*)(C + (size_t)(r + 8) * HH + c) = v1;
            }
        }
    } else {
        // fused h@Wf partial: per-row dot over this warp's 32 cols
        float pr[8];
#pragma unroll
        for (int ii = 0; ii < 8; ii++) pr[ii] = 0.f;
#pragma unroll
        for (int i = 0; i < 4; i++) {
#pragma unroll
            for (int j = 0; j < 4; j++) {
                int c = col0 + wn * 32 + j * 8 + 2 * (lane & 3);
                float b0v = bias[c], b1v = bias[c + 1];
                float wf0 = Wf[c],   wf1 = Wf[c + 1];
                pr[2 * i]     += fmaxf(acc[i][j][0] + b0v, 0.f) * wf0
                               + fmaxf(acc[i][j][1] + b1v, 0.f) * wf1;
                pr[2 * i + 1] += fmaxf(acc[i][j][2] + b0v, 0.f) * wf0
                               + fmaxf(acc[i][j][3] + b1v, 0.f) * wf1;
            }
        }
#pragma unroll
        for (int ii = 0; ii < 8; ii++) {
            pr[ii] += __shfl_xor_sync(0xffffffffu, pr[ii], 1);
            pr[ii] += __shfl_xor_sync(0xffffffffu, pr[ii], 2);
        }
        if ((lane & 3) == 0) {
            int slot = blockIdx.x * 4 + wn;   // 8 slots (2 colblocks x 4 warp_n)
#pragma unroll
            for (int i = 0; i < 4; i++) {
                int r = row0 + wm * 64 + i * 16 + (lane >> 2);
                g_part[(size_t)slot * NN + r]     = pr[2 * i];
                g_part[(size_t)slot * NN + r + 8] = pr[2 * i + 1];
            }
        }
    }
}

// ---------------------------------------------------------------------------
// JAX PARTITIONABLE threefry-2x32, key(42): lanes (hi=0)+k0, (lo=i)+k1;
// 20 rounds; 32-bit draw = out0 ^ out1.  (Validated R7.)
// ---------------------------------------------------------------------------
__device__ __forceinline__ uint32_t rotl32(uint32_t x, int d) {
    return (x << d) | (x >> (32 - d));
}

__device__ __forceinline__ float jax_uniform_u(uint32_t i)
{
    const uint32_t k0 = 0u, k1 = 42u;
    const uint32_t k2 = 0x1BD11BDAu ^ k0 ^ k1;
    uint32_t x0 = k0;
    uint32_t x1 = i + k1;
#define TF_ROUND(r) { x0 += x1; x1 = rotl32(x1, (r)) ^ x0; }
#define TF_G(a,b,c,d) TF_ROUND(a) TF_ROUND(b) TF_ROUND(c) TF_ROUND(d)
    TF_G(13, 15, 26, 6)   x0 += k1; x1 += k2 + 1u;
    TF_G(17, 29, 16, 24)  x0 += k2; x1 += k0 + 2u;
    TF_G(13, 15, 26, 6)   x0 += k0; x1 += k1 + 3u;
    TF_G(17, 29, 16, 24)  x0 += k1; x1 += k2 + 4u;
    TF_G(13, 15, 26, 6)   x0 += k2; x1 += k0 + 5u;
#undef TF_G
#undef TF_ROUND
    uint32_t bits = x0 ^ x1;
    float f = __uint_as_float((bits >> 9) | 0x3f800000u) - 1.0f;
    float u = f * (1.0f - 1e-20f) + 1e-20f;
    return fmaxf(u, 1e-20f);
}

// ---------------------------------------------------------------------------
// Per-segment: logit = sum(8 partials) + bf; softmax over 128; Gumbel-max.
// One 128-thread block per segment. Tie-break: higher index wins.
// ---------------------------------------------------------------------------
__global__ void __launch_bounds__(SEG) final_kernel(
    const float* __restrict__ bf, float* __restrict__ out)
{
    __shared__ float red[SEG];
    __shared__ int   redi[SEG];
    __shared__ float sprob[SEG];
    __shared__ float s_sum;

    const int seg  = blockIdx.x;
    const int t    = threadIdx.x;
    const int node = seg * SEG + t;

    float s = 0.f;
#pragma unroll
    for (int k = 0; k < 8; k++) s += g_part[(size_t)k * NN + node];
    float logit = s + bf[0];
    float e = expf(logit);

    red[t] = e;
    __syncthreads();
#pragma unroll
    for (int st = SEG / 2; st > 0; st >>= 1) {
        if (t < st) red[t] += red[t + st];
        __syncthreads();
    }
    if (t == 0) s_sum = red[0];
    __syncthreads();

    float prob = e / s_sum;
    sprob[t] = prob;

    float u = jax_uniform_u((uint32_t)node);
    float g = -logf(-logf(u));
    float score = logf(prob) + g;

    red[t] = score; redi[t] = t;
    __syncthreads();
#pragma unroll
    for (int st = SEG / 2; st > 0; st >>= 1) {
        if (t < st) {
            float s2 = red[t + st]; int i2 = redi[t + st];
            if (s2 > red[t] || (s2 == red[t] && i2 > redi[t])) { red[t] = s2; redi[t] = i2; }
        }
        __syncthreads();
    }

    if (t == 0) {
        int win = redi[0];
        out[seg]            = sprob[win];
        out[BSEG + seg]     = (float)win;
        out[2 * BSEG + seg] = (float)(seg * SEG + win);
    }
}

// ---------------------------------------------------------------------------
extern "C" void kernel_launch(void* const* d_in, const int* in_sizes, int n_in,
                              void* d_out, int out_size)
{
    (void)out_size;
    const float *X, *W0, *b0, *W1, *b1, *W2, *b2, *Wf, *bf;
    if (n_in > 0 && in_sizes[0] == NN * DIN) {
        X  = (const float*)d_in[0];
        W0 = (const float*)d_in[1]; b0 = (const float*)d_in[2];
        W1 = (const float*)d_in[3]; b1 = (const float*)d_in[4];
        W2 = (const float*)d_in[5]; b2 = (const float*)d_in[6];
        Wf = (const float*)d_in[7]; bf = (const float*)d_in[8];
    } else {
        W0 = (const float*)d_in[0];
        W1 = (const float*)d_in[1];
        W2 = (const float*)d_in[2];
        Wf = (const float*)d_in[3];
        X  = (const float*)d_in[4];
        b0 = (const float*)d_in[5]; b1 = (const float*)d_in[6];
        b2 = (const float*)d_in[7]; bf = (const float*)d_in[9];
    }
    float* out = (float*)d_out;

    float *h1, *h2;
    cudaGetSymbolAddress((void**)&h1, g_h1);
    cudaGetSymbolAddress((void**)&h2, g_h2);

    dim3 grid(2, NN / 128);   // col-major-adjacent blocks share A tiles in L2
    gemm_tf32<DIN, false><<<grid, 256>>>(X,  W0, b0, nullptr, h1);
    gemm_tf32<HH,  false><<<grid, 256>>>(h1, W1, b1, nullptr, h2);
    gemm_tf32<HH,  true ><<<grid, 256>>>(h2, W2, b2, Wf, nullptr);
    final_kernel<<<BSEG, SEG>>>(bf, out);
}

// round 9
// speedup vs baseline: 1.8572x; 1.3681x over previous
#include <cuda_runtime.h>
#include <cuda_bf16.h>
#include <cstdint>

#define NN   524288
#define BSEG 4096
#define SEG  128
#define DIN  128
#define HH   256

// Static device scratch (alloc-free rules).
// h stored pre-split as k-pair-packed bf16 hi/lo: uint2 = (hi0|hi1<<16, lo0|lo1<<16)
__device__ uint2 g_hp1[(size_t)NN * (HH / 2)];
__device__ uint2 g_hp2[(size_t)NN * (HH / 2)];
__device__ float g_part[(size_t)8 * NN];          // fused logit partials
__device__ uint2 g_wp0[(size_t)(DIN / 2) * HH];   // pre-split weights
__device__ uint2 g_wp1[(size_t)(HH / 2) * HH];
__device__ uint2 g_wp2[(size_t)(HH / 2) * HH];

// ---------------------------------------------------------------------------
// bf16 two-term split: x ~= hi + lo, repr error ~2^-18 |x|.
// ---------------------------------------------------------------------------
__device__ __forceinline__ void bsplit(float x, uint32_t& h, uint32_t& l) {
    __nv_bfloat16 bh = __float2bfloat16_rn(x);
    float r = x - __bfloat162float(bh);
    __nv_bfloat16 bl = __float2bfloat16_rn(r);
    h = (uint32_t)__bfloat16_as_ushort(bh);
    l = (uint32_t)__bfloat16_as_ushort(bl);
}
__device__ __forceinline__ uint2 pack2(float x0, float x1) {
    uint32_t h0, l0, h1, l1;
    bsplit(x0, h0, l0); bsplit(x1, h1, l1);
    return make_uint2(h0 | (h1 << 16), l0 | (l1 << 16));
}

// Pre-split a weight matrix W[K,256] into k-pair-packed uint2 [K/2][256].
__global__ void split_w_kernel(const float* __restrict__ W, uint2* __restrict__ o, int kpairs) {
    int idx = blockIdx.x * blockDim.x + threadIdx.x;
    if (idx >= kpairs * HH) return;
    int kp = idx / HH, n = idx % HH;
    o[idx] = pack2(W[(size_t)(2 * kp) * HH + n], W[(size_t)(2 * kp + 1) * HH + n]);
}

__device__ __forceinline__ void mma16(float* c, const uint32_t* a, uint32_t b0, uint32_t b1) {
    asm volatile("mma.sync.aligned.m16n8k16.row.col.f32.bf16.bf16.f32 "
        "{%0,%1,%2,%3}, {%4,%5,%6,%7}, {%8,%9}, {%0,%1,%2,%3};"
        : "+f"(c[0]), "+f"(c[1]), "+f"(c[2]), "+f"(c[3])
        : "r"(a[0]), "r"(a[1]), "r"(a[2]), "r"(a[3]), "r"(b0), "r"(b1));
}

// ---------------------------------------------------------------------------
// bf16x3 tensor-core layer: C = relu(A @ W + b)  (or fused logit partials).
// Block 128x128, BK=32, 8 warps (wm 0..1 x wn 0..3), warp tile 64x32.
// A: fp32 (layer1, split at load) or packed uint2 (layers 2/3, direct copy).
// W: packed uint2 from prep kernel. Output: packed uint2 h, or g_part (FUSE).
// ---------------------------------------------------------------------------
template<int HIN, bool AFP32, bool FUSE>
__global__ void __launch_bounds__(256, 2) gemm_bf16x3(
    const void* __restrict__ Ain, const uint2* __restrict__ Wp,
    const float* __restrict__ bias, const float* __restrict__ Wf,
    uint2* __restrict__ C)
{
    __shared__ uint2 As[128][20];   // [row][kpair 0..15], pad 20: conflict-free
    __shared__ uint2 Bs[16][132];   // [kpair][n 0..127], pad 132: conflict-free

    const int t    = threadIdx.x;
    const int lane = t & 31;
    const int w    = t >> 5;
    const int wm   = w >> 2;
    const int wn   = w & 3;
    const int row0 = blockIdx.y * 128;
    const int col0 = blockIdx.x * 128;

    float acc[4][4][4];
#pragma unroll
    for (int i = 0; i < 4; i++)
#pragma unroll
        for (int j = 0; j < 4; j++)
#pragma unroll
            for (int q = 0; q < 4; q++) acc[i][j][q] = 0.f;

    const int ar = t >> 1;            // A load: one row per 2 threads
    const int ako = (t & 1) * 16;     // 16 k (8 kpairs) each
    const int bkp = t >> 5;           // B load rows
    const int bn0 = (t & 31) * 4;     // 4 n each

    for (int k0 = 0; k0 < HIN; k0 += 32) {
        if (AFP32) {
            const float* a = (const float*)Ain + (size_t)(row0 + ar) * HIN + k0 + ako;
#pragma unroll
            for (int q = 0; q < 4; q++) {
                float4 v = *(const float4*)(a + q * 4);
                As[ar][ako / 2 + q * 2]     = pack2(v.x, v.y);
                As[ar][ako / 2 + q * 2 + 1] = pack2(v.z, v.w);
            }
        } else {
            const uint2* a = (const uint2*)Ain + (size_t)(row0 + ar) * (HIN / 2) + k0 / 2 + ako / 2;
#pragma unroll
            for (int q = 0; q < 4; q++)
                *(uint4*)&As[ar][ako / 2 + q * 2] = *(const uint4*)(a + q * 2);
        }
#pragma unroll
        for (int p = 0; p < 2; p++) {
            int kp = p * 8 + bkp;
            const uint2* src = Wp + (size_t)(k0 / 2 + kp) * HH + col0 + bn0;
            *(uint4*)&Bs[kp][bn0]     = *(const uint4*)(src);
            *(uint4*)&Bs[kp][bn0 + 2] = *(const uint4*)(src + 2);
        }
        __syncthreads();

#pragma unroll
        for (int kk = 0; kk < 2; kk++) {
            const int kpb = kk * 8;
            uint32_t ahi[4][4], alo[4][4];
#pragma unroll
            for (int i = 0; i < 4; i++) {
                int r = wm * 64 + i * 16 + (lane >> 2);
                int c = kpb + (lane & 3);
                uint2 q0 = As[r][c];
                uint2 q1 = As[r + 8][c];
                uint2 q2 = As[r][c + 4];
                uint2 q3 = As[r + 8][c + 4];
                ahi[i][0] = q0.x; ahi[i][1] = q1.x; ahi[i][2] = q2.x; ahi[i][3] = q3.x;
                alo[i][0] = q0.y; alo[i][1] = q1.y; alo[i][2] = q2.y; alo[i][3] = q3.y;
            }
#pragma unroll
            for (int j = 0; j < 4; j++) {
                int n  = wn * 32 + j * 8 + (lane >> 2);
                int kp = kpb + (lane & 3);
                uint2 p0 = Bs[kp][n];
                uint2 p1 = Bs[kp + 4][n];
#pragma unroll
                for (int i = 0; i < 4; i++) mma16(acc[i][j], ahi[i], p0.x, p1.x);
#pragma unroll
                for (int i = 0; i < 4; i++) mma16(acc[i][j], ahi[i], p0.y, p1.y);
#pragma unroll
                for (int i = 0; i < 4; i++) mma16(acc[i][j], alo[i], p0.x, p1.x);
            }
        }
        __syncthreads();
    }

    if (!FUSE) {
#pragma unroll
        for (int i = 0; i < 4; i++) {
            int r = row0 + wm * 64 + i * 16 + (lane >> 2);
#pragma unroll
            for (int j = 0; j < 4; j++) {
                int c = col0 + wn * 32 + j * 8 + 2 * (lane & 3);
                float v0 = fmaxf(acc[i][j][0] + bias[c],     0.f);
                float v1 = fmaxf(acc[i][j][1] + bias[c + 1], 0.f);
                float v2 = fmaxf(acc[i][j][2] + bias[c],     0.f);
                float v3 = fmaxf(acc[i][j][3] + bias[c + 1], 0.f);
                C[(size_t)r * (HH / 2) + c / 2]       = pack2(v0, v1);
                C[(size_t)(r + 8) * (HH / 2) + c / 2] = pack2(v2, v3);
            }
        }
    } else {
        float pr[8];
#pragma unroll
        for (int ii = 0; ii < 8; ii++) pr[ii] = 0.f;
#pragma unroll
        for (int i = 0; i < 4; i++) {
#pragma unroll
            for (int j = 0; j < 4; j++) {
                int c = col0 + wn * 32 + j * 8 + 2 * (lane & 3);
                float b0v = bias[c], b1v = bias[c + 1];
                float wf0 = Wf[c],   wf1 = Wf[c + 1];
                pr[2 * i]     += fmaxf(acc[i][j][0] + b0v, 0.f) * wf0
                               + fmaxf(acc[i][j][1] + b1v, 0.f) * wf1;
                pr[2 * i + 1] += fmaxf(acc[i][j][2] + b0v, 0.f) * wf0
                               + fmaxf(acc[i][j][3] + b1v, 0.f) * wf1;
            }
        }
#pragma unroll
        for (int ii = 0; ii < 8; ii++) {
            pr[ii] += __shfl_xor_sync(0xffffffffu, pr[ii], 1);
            pr[ii] += __shfl_xor_sync(0xffffffffu, pr[ii], 2);
        }
        if ((lane & 3) == 0) {
            int slot = blockIdx.x * 4 + wn;
#pragma unroll
            for (int i = 0; i < 4; i++) {
                int r = row0 + wm * 64 + i * 16 + (lane >> 2);
                g_part[(size_t)slot * NN + r]     = pr[2 * i];
                g_part[(size_t)slot * NN + r + 8] = pr[2 * i + 1];
            }
        }
    }
}

// ---------------------------------------------------------------------------
// JAX partitionable threefry-2x32, key(42); bits = out0 ^ out1. (Validated R7.)
// ---------------------------------------------------------------------------
__device__ __forceinline__ uint32_t rotl32(uint32_t x, int d) {
    return (x << d) | (x >> (32 - d));
}

__device__ __forceinline__ float jax_uniform_u(uint32_t i)
{
    const uint32_t k0 = 0u, k1 = 42u;
    const uint32_t k2 = 0x1BD11BDAu ^ k0 ^ k1;
    uint32_t x0 = k0;
    uint32_t x1 = i + k1;
#define TF_ROUND(r) { x0 += x1; x1 = rotl32(x1, (r)) ^ x0; }
#define TF_G(a,b,c,d) TF_ROUND(a) TF_ROUND(b) TF_ROUND(c) TF_ROUND(d)
    TF_G(13, 15, 26, 6)   x0 += k1; x1 += k2 + 1u;
    TF_G(17, 29, 16, 24)  x0 += k2; x1 += k0 + 2u;
    TF_G(13, 15, 26, 6)   x0 += k0; x1 += k1 + 3u;
    TF_G(17, 29, 16, 24)  x0 += k1; x1 += k2 + 4u;
    TF_G(13, 15, 26, 6)   x0 += k2; x1 += k0 + 5u;
#undef TF_G
#undef TF_ROUND
    uint32_t bits = x0 ^ x1;
    float f = __uint_as_float((bits >> 9) | 0x3f800000u) - 1.0f;
    float u = f * (1.0f - 1e-20f) + 1e-20f;
    return fmaxf(u, 1e-20f);
}

// ---------------------------------------------------------------------------
// Per-segment softmax + Gumbel-max over the 8 logit partials.
// ---------------------------------------------------------------------------
__global__ void __launch_bounds__(SEG) final_kernel(
    const float* __restrict__ bf, float* __restrict__ out)
{
    __shared__ float red[SEG];
    __shared__ int   redi[SEG];
    __shared__ float sprob[SEG];
    __shared__ float s_sum;

    const int seg  = blockIdx.x;
    const int t    = threadIdx.x;
    const int node = seg * SEG + t;

    float s = 0.f;
#pragma unroll
    for (int k = 0; k < 8; k++) s += g_part[(size_t)k * NN + node];
    float logit = s + bf[0];
    float e = expf(logit);

    red[t] = e;
    __syncthreads();
#pragma unroll
    for (int st = SEG / 2; st > 0; st >>= 1) {
        if (t < st) red[t] += red[t + st];
        __syncthreads();
    }
    if (t == 0) s_sum = red[0];
    __syncthreads();

    float prob = e / s_sum;
    sprob[t] = prob;

    float u = jax_uniform_u((uint32_t)node);
    float g = -logf(-logf(u));
    float score = logf(prob) + g;

    red[t] = score; redi[t] = t;
    __syncthreads();
#pragma unroll
    for (int st = SEG / 2; st > 0; st >>= 1) {
        if (t < st) {
            float s2 = red[t + st]; int i2 = redi[t + st];
            if (s2 > red[t] || (s2 == red[t] && i2 > redi[t])) { red[t] = s2; redi[t] = i2; }
        }
        __syncthreads();
    }

    if (t == 0) {
        int win = redi[0];
        out[seg]            = sprob[win];
        out[BSEG + seg]     = (float)win;
        out[2 * BSEG + seg] = (float)(seg * SEG + win);
    }
}

// ---------------------------------------------------------------------------
extern "C" void kernel_launch(void* const* d_in, const int* in_sizes, int n_in,
                              void* d_out, int out_size)
{
    (void)out_size;
    const float *X, *W0, *b0, *W1, *b1, *W2, *b2, *Wf, *bf;
    if (n_in > 0 && in_sizes[0] == NN * DIN) {
        X  = (const float*)d_in[0];
        W0 = (const float*)d_in[1]; b0 = (const float*)d_in[2];
        W1 = (const float*)d_in[3]; b1 = (const float*)d_in[4];
        W2 = (const float*)d_in[5]; b2 = (const float*)d_in[6];
        Wf = (const float*)d_in[7]; bf = (const float*)d_in[8];
    } else {
        W0 = (const float*)d_in[0];
        W1 = (const float*)d_in[1];
        W2 = (const float*)d_in[2];
        Wf = (const float*)d_in[3];
        X  = (const float*)d_in[4];
        b0 = (const float*)d_in[5]; b1 = (const float*)d_in[6];
        b2 = (const float*)d_in[7]; bf = (const float*)d_in[9];
    }
    float* out = (float*)d_out;

    uint2 *hp1, *hp2, *wp0, *wp1, *wp2;
    cudaGetSymbolAddress((void**)&hp1, g_hp1);
    cudaGetSymbolAddress((void**)&hp2, g_hp2);
    cudaGetSymbolAddress((void**)&wp0, g_wp0);
    cudaGetSymbolAddress((void**)&wp1, g_wp1);
    cudaGetSymbolAddress((void**)&wp2, g_wp2);

    split_w_kernel<<<(DIN / 2 * HH + 255) / 256, 256>>>(W0, wp0, DIN / 2);
    split_w_kernel<<<(HH / 2 * HH + 255) / 256, 256>>>(W1, wp1, HH / 2);
    split_w_kernel<<<(HH / 2 * HH + 255) / 256, 256>>>(W2, wp2, HH / 2);

    dim3 grid(2, NN / 128);
    gemm_bf16x3<DIN, true,  false><<<grid, 256>>>(X,   wp0, b0, nullptr, hp1);
    gemm_bf16x3<HH,  false, false><<<grid, 256>>>(hp1, wp1, b1, nullptr, hp2);
    gemm_bf16x3<HH,  false, true ><<<grid, 256>>>(hp2, wp2, b2, Wf, nullptr);
    final_kernel<<<BSEG, SEG>>>(bf, out);
}